// round 9
// baseline (speedup 1.0000x reference)
#include <cuda_runtime.h>
#include <math.h>

// ---------------- problem constants ----------------
#define cU 160
#define cL 512
#define cN 400
#define cS 16
#define cW 64
#define CVIOL 20000.0f
#define NITERS 500
#define NPOWER 30

// ---------------- grid constants ----------------
#define NB 132
#define NT 256
#define NTH (NB*NT)

// ---------------- X (primal) layout ----------------
#define OX_P   0
#define OX_RU  160
#define OX_RD  320
#define OX_PU  480
#define OX_PD  3040
#define OX_SU  5600
#define OX_SD  6000
#define XTOT   6400

// ---------------- Y (dual ineq) layout ----------------
#define OY1 0
#define OY2 160
#define OY3 320
#define OY4 832
#define OY5 1344
#define OY6 3904
#define OY7 6464
#define OY8 14656
#define YTOT 22848

// ---------------- device state (mutable: ALWAYS accessed via .cg) ----------------
__device__ __align__(16) float g_X[XTOT];
__device__ __align__(16) float g_XBP[cU];        // xbar p
__device__ __align__(16) float g_XBC[cU*cS];     // xbar (pu - pd)
__device__ __align__(16) float g_XBE[cN];        // xbar (su - sd)
__device__ __align__(16) float g_Y[YTOT];
__device__ __align__(16) float g_s78[cL*cS];
__device__ float g_s78s[cL];
__device__ float g_t[cL];
__device__ float g_z1, g_z2[cS], g_z2sum, g_tau;
__device__ float g_part_p[NB], g_part_e[NB], g_part_c[80*cS], g_part_ss[NB];

// immutable after setup (normal loads -> L1-cached)
__device__ float g_Hg[cL*cU];
__device__ float g_HgT[cU*cL];
__device__ float g_PTT[cN*cL];
__device__ float g_c3[cL], g_c4[cL];
__device__ __align__(16) float g_b7[cL*cS];
__device__ __align__(16) float g_b8[cL*cS];
__device__ int   g_gidx[cU];
__device__ int   g_widx[cW];
__device__ float g_beq1, g_beq2[cS];

// ---------------- barrier state ----------------
__device__ unsigned g_arrive[NB*8];   // stride-8 padded arrival slots
__device__ unsigned g_epoch = 0;      // persistent round base across launches

// ---------------- cg helpers ----------------
__device__ __forceinline__ float  ldcg (const float*  p){ return __ldcg(p); }
__device__ __forceinline__ float4 ldcg4(const float4* p){ return __ldcg(p); }
__device__ __forceinline__ void   stcg (float* p, float v){ __stcg(p, v); }

// ---------------- flat-arrival grid barrier (no atomics, no L1 flush) ----------------
__device__ __forceinline__ void gsync(unsigned rnd) {
    __syncthreads();
    if (threadIdx.x < 32) {
        const int lane = threadIdx.x;
        if (lane == 0) {
            asm volatile("st.release.gpu.global.u32 [%0], %1;"
                         :: "l"(&g_arrive[blockIdx.x * 8]), "r"(rnd) : "memory");
        }
        const unsigned* p0 = &g_arrive[(lane)              * 8];
        const unsigned* p1 = &g_arrive[(lane + 32)         * 8];
        const unsigned* p2 = &g_arrive[(lane + 64)         * 8];
        const unsigned* p3 = &g_arrive[(lane + 96)         * 8];
        const unsigned* p4 = &g_arrive[(128 + (lane & 3))  * 8];
        for (;;) {
            unsigned a, b, c, d, e;
            asm volatile("ld.acquire.gpu.global.u32 %0, [%1];" : "=r"(a) : "l"(p0) : "memory");
            asm volatile("ld.acquire.gpu.global.u32 %0, [%1];" : "=r"(b) : "l"(p1) : "memory");
            asm volatile("ld.acquire.gpu.global.u32 %0, [%1];" : "=r"(c) : "l"(p2) : "memory");
            asm volatile("ld.acquire.gpu.global.u32 %0, [%1];" : "=r"(d) : "l"(p3) : "memory");
            asm volatile("ld.acquire.gpu.global.u32 %0, [%1];" : "=r"(e) : "l"(p4) : "memory");
            bool ok = ((int)(a - rnd) >= 0) && ((int)(b - rnd) >= 0) &&
                      ((int)(c - rnd) >= 0) && ((int)(d - rnd) >= 0) &&
                      ((int)(e - rnd) >= 0);
            if (__all_sync(0xffffffffu, ok)) break;
            __nanosleep(40);
        }
    }
    __syncthreads();
}

// ---------------- warp helpers ----------------
__device__ __forceinline__ float wallred(float v) {
#pragma unroll
    for (int o = 16; o; o >>= 1) v += __shfl_xor_sync(0xffffffffu, v, o);
    return v;
}

__device__ __forceinline__ void allred16(float (&v)[16]) {
#pragma unroll
    for (int o = 16; o; o >>= 1) {
#pragma unroll
        for (int k = 0; k < 16; k++) v[k] += __shfl_xor_sync(0xffffffffu, v[k], o);
    }
}

__device__ __forceinline__ float pick16(const float (&a)[16], int s) {
    float r = a[0];
#pragma unroll
    for (int k = 1; k < 16; k++) r = (s == k) ? a[k] : r;
    return r;
}

__device__ __forceinline__ void fma16cg(float (&acc)[16], float h, const float4* p) {
    float4 a0 = __ldcg(p), a1 = __ldcg(p+1), a2 = __ldcg(p+2), a3 = __ldcg(p+3);
    acc[0]  = fmaf(h, a0.x, acc[0]);  acc[1]  = fmaf(h, a0.y, acc[1]);
    acc[2]  = fmaf(h, a0.z, acc[2]);  acc[3]  = fmaf(h, a0.w, acc[3]);
    acc[4]  = fmaf(h, a1.x, acc[4]);  acc[5]  = fmaf(h, a1.y, acc[5]);
    acc[6]  = fmaf(h, a1.z, acc[6]);  acc[7]  = fmaf(h, a1.w, acc[7]);
    acc[8]  = fmaf(h, a2.x, acc[8]);  acc[9]  = fmaf(h, a2.y, acc[9]);
    acc[10] = fmaf(h, a2.z, acc[10]); acc[11] = fmaf(h, a2.w, acc[11]);
    acc[12] = fmaf(h, a3.x, acc[12]); acc[13] = fmaf(h, a3.y, acc[13]);
    acc[14] = fmaf(h, a3.z, acc[14]); acc[15] = fmaf(h, a3.w, acc[15]);
}

// transposed smem read: dsh_t[k*160 + u], lane-consecutive u -> conflict-free LDS.32
__device__ __forceinline__ void fma16sh_t(float (&acc)[16], float h, const float* base_u) {
#pragma unroll
    for (int k = 0; k < 16; k++) acc[k] = fmaf(h, base_u[k * cU], acc[k]);
}

// ---------------- Phase A ----------------
// u-part: blocks 0..79 (2 u/block, 4 warps/u); n-part: blocks 80..131 (<=1 row/warp).
// Non-POW also applies the fused y1/y2/y5/y6 dual updates and writes packed xbar arrays.
template<bool POW>
__device__ __forceinline__ void phaseA(int blk, int wId, int lane, float tau,
                                       const float* __restrict__ Cost,
                                       const float* __restrict__ Cru,
                                       const float* __restrict__ Crd,
                                       const float* __restrict__ Pmax,
                                       float* sA, float* shp, float* shc,
                                       float* sh8, float* sh8b, float* s78s_sh)
{
    const float sig = tau;
    if (blk < 80) {
        const int u  = 2*blk + (wId >> 2);
        const int Lb = (wId & 3) * 128;
        const bool comb = ((wId & 3) == 0);
        // prefetch duals before the dot (latency hidden under FMAs)
        float y5v = 0.f, y6v = 0.f, y1u = 0.f, y2u = 0.f, z1 = 0.f, z2s = 0.f;
        if (comb) {
            if (lane < cS) {
                y5v = ldcg(&g_Y[OY5 + u*cS + lane]);
                y6v = ldcg(&g_Y[OY6 + u*cS + lane]);
                z2s = ldcg(&g_z2[lane]);
            }
            y1u = ldcg(&g_Y[OY1 + u]); y2u = ldcg(&g_Y[OY2 + u]);
            z1  = ldcg(&g_z1);
        }
        float accT = 0.f;
        float acc[16];
#pragma unroll
        for (int k = 0; k < 16; k++) acc[k] = 0.f;
        const float* hr = g_HgT + (size_t)u * cL + Lb;
#pragma unroll
        for (int j = 0; j < 4; j++) {
            int l = lane + 32*j;
            float h = hr[l];                              // L1-cached
            accT = fmaf(h, ldcg(&g_t[Lb + l]), accT);
            fma16cg(acc, h, reinterpret_cast<const float4*>(g_s78 + (size_t)(Lb + l) * cS));
        }
        accT = wallred(accT);
        allred16(acc);
        if (lane < 16) sA[wId*17 + lane] = pick16(acc, lane);
        if (lane == 0) sA[wId*17 + 16] = accT;
        __syncthreads();
        if (comb) {
            const int half = wId >> 2;
            const int b0 = (half*4) * 17;
            float aT = sA[b0+16] + sA[b0+17+16] + sA[b0+34+16] + sA[b0+51+16];
            float aS = 0.f;
            if (lane < 16) aS = sA[b0+lane] + sA[b0+17+lane] + sA[b0+34+lane] + sA[b0+51+lane];
            float sum5 = wallred((lane < cS) ? y5v : 0.f);
            float sum6 = wallred((lane < cS) ? y6v : 0.f);
            float ssv = 0.f;
            float xb_p = 0.f, xb_ru = 0.f, xb_rd = 0.f;
            if (lane == 0) {
                float gp  = y1u - y2u + aT + z1;
                float gru = y1u - sum5;
                float grd = y2u - sum6;
                if (POW) {
                    stcg(&g_X[OX_P + u], gp); stcg(&g_X[OX_RU + u], gru); stcg(&g_X[OX_RD + u], grd);
                    ssv += gp*gp + gru*gru + grd*grd;
                    shp[half] = gp;
                } else {
                    float x = ldcg(&g_X[OX_P + u]);
                    float xn = fmaxf(x - tau*(Cost[u] + gp), 0.f);
                    xb_p = 2.f*xn - x;
                    stcg(&g_X[OX_P + u], xn); stcg(&g_XBP[u], xb_p); shp[half] = xb_p;
                    x = ldcg(&g_X[OX_RU + u]); xn = fmaxf(x - tau*(Cru[u] + gru), 0.f);
                    xb_ru = 2.f*xn - x;
                    stcg(&g_X[OX_RU + u], xn);
                    x = ldcg(&g_X[OX_RD + u]); xn = fmaxf(x - tau*(Crd[u] + grd), 0.f);
                    xb_rd = 2.f*xn - x;
                    stcg(&g_X[OX_RD + u], xn);
                }
            }
            if (!POW) {
                xb_ru = __shfl_sync(0xffffffffu, xb_ru, 0);
                xb_rd = __shfl_sync(0xffffffffu, xb_rd, 0);
            }
            if (lane < cS) {
                float gpu_ = y5v + aS + z2s;
                float gpd_ = y6v - aS - z2s;
                int iu = OX_PU + u*cS + lane, id = OX_PD + u*cS + lane;
                if (POW) {
                    stcg(&g_X[iu], gpu_); stcg(&g_X[id], gpd_);
                    ssv += gpu_*gpu_ + gpd_*gpd_;
                    shc[half*cS + lane] = gpu_ - gpd_;
                } else {
                    float x = ldcg(&g_X[iu]); float xn = fmaxf(x - tau*gpu_, 0.f);
                    float xbu = 2.f*xn - x; stcg(&g_X[iu], xn);
                    x = ldcg(&g_X[id]); xn = fmaxf(x - tau*gpd_, 0.f);
                    float xbd = 2.f*xn - x; stcg(&g_X[id], xn);
                    stcg(&g_XBC[u*cS + lane], xbu - xbd);
                    shc[half*cS + lane] = xbu - xbd;
                    float y5n = fmaxf(y5v + sig*(xbu - xb_ru), 0.f);
                    float y6n = fmaxf(y6v + sig*(xbd - xb_rd), 0.f);
                    stcg(&g_Y[OY5 + u*cS + lane], y5n);
                    stcg(&g_Y[OY6 + u*cS + lane], y6n);
                }
            }
            if (!POW && lane == 0) {
                float y1n = fmaxf(y1u + sig*(xb_p + xb_ru - Pmax[u]), 0.f);
                float y2n = fmaxf(y2u + sig*(xb_rd - xb_p), 0.f);
                stcg(&g_Y[OY1 + u], y1n); stcg(&g_Y[OY2 + u], y2n);
            }
            if (POW) {
                float w = wallred(ssv);
                if (lane == 0) sh8[half] = w;
            }
        }
        __syncthreads();
        if (wId == 0) {
            if (lane == 0) stcg(&g_part_p[blk], shp[0] + shp[1]);
            if (lane < cS) stcg(&g_part_c[blk*cS + lane], shc[lane] + shc[cS + lane]);
            if (POW && lane == 0) stcg(&g_part_ss[blk], sh8[0] + sh8[1]);
        }
    } else {
        for (int i = threadIdx.x; i < cL; i += NT) s78s_sh[i] = ldcg(&g_s78s[i]);
        __syncthreads();
        const int wn = (blk - 80)*8 + wId;   // 0..415, active < 400
        float agg_e = 0.f, agg_ss = 0.f;
        if (wn < cN) {
            float zs = ldcg(&g_z2sum);
            float a0 = 0.f;
            const float* r0 = g_PTT + (size_t)wn * cL;
#pragma unroll 4
            for (int l = lane; l < cL; l += 32) a0 = fmaf(r0[l], s78s_sh[l], a0);
            a0 = wallred(a0);
            if (lane == 0) {
                float gsu = a0 + zs, gsd = -a0 - zs;
                if (POW) {
                    stcg(&g_X[OX_SU + wn], gsu); stcg(&g_X[OX_SD + wn], gsd);
                    agg_ss = gsu*gsu + gsd*gsd;
                    agg_e  = gsu - gsd;
                } else {
                    float x = ldcg(&g_X[OX_SU + wn]); float xn = fmaxf(x - tau*(CVIOL + gsu), 0.f);
                    float xbu = 2.f*xn - x; stcg(&g_X[OX_SU + wn], xn);
                    x = ldcg(&g_X[OX_SD + wn]); xn = fmaxf(x - tau*(CVIOL + gsd), 0.f);
                    float xbd = 2.f*xn - x; stcg(&g_X[OX_SD + wn], xn);
                    stcg(&g_XBE[wn], xbu - xbd);
                    agg_e = xbu - xbd;
                }
            }
        }
        if (lane == 0) { sh8[wId] = agg_e; sh8b[wId] = agg_ss; }
        __syncthreads();
        if (wId == 0 && lane == 0) {
            float se = 0.f, ss = 0.f;
#pragma unroll
            for (int k = 0; k < 8; k++) { se += sh8[k]; ss += sh8b[k]; }
            stcg(&g_part_e[blk], se);
            if (POW) stcg(&g_part_ss[blk], ss);
        }
    }
}

// ---------------- Phase B ----------------
// l-part: blocks 0..127, 4 l/block, 2 warps per l (u/n halves, smem combine).
// POW: blocks 128..131 write u-y rows (scaled); eq-duals: block 128 warp 7.
template<bool POW>
__device__ __forceinline__ void phaseB(int blk, int wId, int lane, float sig,
                                       const float* __restrict__ PTDF,
                                       float* dsh_t, float* sdsh, float* psh, float* sB)
{
    float inv = 1.f;
    if (POW) {
        float a = 0.f;
#pragma unroll
        for (int k = 0; k < 4; k++) a += ldcg(&g_part_ss[lane + 32*k]);
        if (lane < 4) a += ldcg(&g_part_ss[128 + lane]);
        a = wallred(a);
        inv = rsqrtf(a);
    }
    if (blk < 128) {
        // ---- staging ----
        if (POW) {
            for (int c = threadIdx.x; c < (cU*cS/4); c += NT) {
                float4 a = ldcg4(reinterpret_cast<const float4*>(g_X + OX_PU) + c);
                float4 b = ldcg4(reinterpret_cast<const float4*>(g_X + OX_PD) + c);
                int u = c >> 2, s0 = (c & 3) * 4;
                dsh_t[(s0+0)*cU + u] = (a.x - b.x) * inv;
                dsh_t[(s0+1)*cU + u] = (a.y - b.y) * inv;
                dsh_t[(s0+2)*cU + u] = (a.z - b.z) * inv;
                dsh_t[(s0+3)*cU + u] = (a.w - b.w) * inv;
            }
            for (int i = threadIdx.x; i < cN; i += NT)
                sdsh[i] = (ldcg(&g_X[OX_SU + i]) - ldcg(&g_X[OX_SD + i])) * inv;
            for (int i = threadIdx.x; i < cU; i += NT)
                psh[i] = ldcg(&g_X[OX_P + i]) * inv;
        } else {
            for (int c = threadIdx.x; c < (cU*cS/4); c += NT) {
                float4 d = ldcg4(reinterpret_cast<const float4*>(g_XBC) + c);
                int u = c >> 2, s0 = (c & 3) * 4;
                dsh_t[(s0+0)*cU + u] = d.x;
                dsh_t[(s0+1)*cU + u] = d.y;
                dsh_t[(s0+2)*cU + u] = d.z;
                dsh_t[(s0+3)*cU + u] = d.w;
            }
            for (int i = threadIdx.x; i < cN; i += NT) sdsh[i] = ldcg(&g_XBE[i]);
            for (int i = threadIdx.x; i < cU; i += NT) psh[i] = ldcg(&g_XBP[i]);
        }
        __syncthreads();
        const int l = blk*4 + (wId >> 1);
        const int half = wId & 1;
        // prefetch duals on the combining (half==0) warp
        float y3 = 0.f, y4 = 0.f, y7 = 0.f, y8 = 0.f;
        if (!POW && half == 0) {
            y3 = ldcg(&g_Y[OY3 + l]);
            y4 = ldcg(&g_Y[OY4 + l]);
            if (lane < cS) {
                y7 = ldcg(&g_Y[OY7 + l*cS + lane]);
                y8 = ldcg(&g_Y[OY8 + l*cS + lane]);
            }
        }
        float accF = 0.f, accP = 0.f;
        float acc[16];
#pragma unroll
        for (int k = 0; k < 16; k++) acc[k] = 0.f;
        const float* hr = g_Hg + (size_t)l * cU;
        const int u0 = half * 80;
        for (int u = u0 + lane; u < u0 + 80; u += 32) {
            float h = hr[u];
            accF = fmaf(h, psh[u], accF);
            fma16sh_t(acc, h, dsh_t + u);
        }
        const float* pr = PTDF + (size_t)l * cN;
        const int n0 = half * 200;
#pragma unroll 2
        for (int n = n0 + lane; n < n0 + 200; n += 32) accP = fmaf(pr[n], sdsh[n], accP);
        accF = wallred(accF);
        accP = wallred(accP);
        allred16(acc);
        if (lane < 16) sB[wId*19 + lane] = pick16(acc, lane);
        if (lane == 0) { sB[wId*19 + 16] = accF; sB[wId*19 + 17] = accP; }
        __syncthreads();
        if (half == 0) {
            float fp = sB[wId*19 + 16] + sB[(wId+1)*19 + 16];
            float aP = sB[wId*19 + 17] + sB[(wId+1)*19 + 17];
            float aS = (lane < 16) ? (sB[wId*19 + lane] + sB[(wId+1)*19 + lane]) : 0.f;
            float base = fp + aP;
            float y3n, y4n;
            if (POW) { y3n = fp; y4n = -fp; }
            else {
                y3n = fmaxf(y3 + sig*( fp - g_c3[l]), 0.f);
                y4n = fmaxf(y4 + sig*(-fp - g_c4[l]), 0.f);
            }
            float s78v = 0.f;
            if (lane < cS) {
                float scen = aS + base;
                float y7n, y8n;
                if (POW) { y7n = scen; y8n = -scen; }
                else {
                    y7n = fmaxf(y7 + sig*( scen - g_b7[l*cS + lane]), 0.f);
                    y8n = fmaxf(y8 + sig*(-scen - g_b8[l*cS + lane]), 0.f);
                }
                stcg(&g_Y[OY7 + l*cS + lane], y7n);
                stcg(&g_Y[OY8 + l*cS + lane], y8n);
                s78v = y7n - y8n;
                stcg(&g_s78[l*cS + lane], s78v);
            }
            float s78s = wallred(s78v);
            if (lane == 0) {
                stcg(&g_Y[OY3 + l], y3n);
                stcg(&g_Y[OY4 + l], y4n);
                stcg(&g_s78s[l], s78s);
                stcg(&g_t[l], y3n - y4n + s78s);
            }
        }
    } else {
        if (POW) {
            const int base = (blk - 128)*40 + wId*5;
#pragma unroll
            for (int r = 0; r < 5; r++) {
                const int u = base + r;
                float ru = ldcg(&g_X[OX_RU + u]) * inv;
                float rd = ldcg(&g_X[OX_RD + u]) * inv;
                if (lane == 0) {
                    float p = ldcg(&g_X[OX_P + u]) * inv;
                    stcg(&g_Y[OY1 + u], p + ru);
                    stcg(&g_Y[OY2 + u], rd - p);
                }
                if (lane < cS) {
                    float pu = ldcg(&g_X[OX_PU + u*cS + lane]) * inv;
                    float pd = ldcg(&g_X[OX_PD + u*cS + lane]) * inv;
                    stcg(&g_Y[OY5 + u*cS + lane], pu - ru);
                    stcg(&g_Y[OY6 + u*cS + lane], pd - rd);
                }
            }
        }
        if (blk == 128 && wId == 7) {
            float sp = 0.f;
            for (int b = lane; b < 80; b += 32) sp += ldcg(&g_part_p[b]);
            sp = wallred(sp);
            float se = 0.f;
            for (int b = 80 + lane; b < NB; b += 32) se += ldcg(&g_part_e[b]);
            se = wallred(se);
            int s = lane & 15, h = lane >> 4;
            float sc = 0.f;
#pragma unroll
            for (int b = h*40; b < h*40 + 40; b++) sc += ldcg(&g_part_c[b*cS + s]);
            sc += __shfl_xor_sync(0xffffffffu, sc, 16);
            float ae2 = sc + se;
            float z2n = 0.f;
            if (lane < cS) {
                z2n = POW ? (ae2 * inv) : (ldcg(&g_z2[lane]) + sig*(ae2 - g_beq2[lane]));
                stcg(&g_z2[lane], z2n);
            }
            float zs = wallred((lane < cS) ? z2n : 0.f);
            if (lane == 0) {
                float z1n = POW ? (sp * inv) : (ldcg(&g_z1) + sig*(sp - g_beq1));
                stcg(&g_z1, z1n);
                stcg(&g_z2sum, zs);
            }
        }
    }
}

// ---------------- main persistent kernel ----------------
__global__ void __launch_bounds__(NT, 1)
opf_kernel(const float* __restrict__ w_scen, const float* __restrict__ Pmax,
           const float* __restrict__ Cost, const float* __restrict__ Cru,
           const float* __restrict__ Crd, const float* __restrict__ PTDF,
           const float* __restrict__ node_G, const float* __restrict__ node_W,
           const float* __restrict__ Pd, const float* __restrict__ w_exp,
           const float* __restrict__ Cap, float* __restrict__ out)
{
    __shared__ __align__(16) float dsh_t[cS*cU];
    __shared__ float sdsh[cN];
    __shared__ float psh[cU];
    __shared__ float s78s_sh[cL];
    __shared__ float sA[8*17];
    __shared__ float sB[8*19];
    __shared__ float shp[2], shc[2*cS], sh8[8], sh8b[8];

    const int blk  = blockIdx.x;
    const int tid  = blk * NT + threadIdx.x;
    const int wId  = threadIdx.x >> 5;
    const int lane = threadIdx.x & 31;
    const int gw   = blk * 8 + wId;
    unsigned rnd;
    {
        unsigned e;
        asm volatile("ld.global.cg.u32 %0, [%1];" : "=r"(e) : "l"(&g_epoch));
        rnd = e;
    }

    // ---- setup 1: index extraction + equality rhs ----
    if (gw < cU) {
        int u = gw, f = -1;
        for (int n = lane; n < cN; n += 32)
            if (node_G[n * cU + u] != 0.f) f = n;
#pragma unroll
        for (int o = 16; o; o >>= 1) f = max(f, __shfl_xor_sync(0xffffffffu, f, o));
        if (lane == 0) __stcg(&g_gidx[u], f);
    } else if (gw < cU + cW) {
        int w = gw - cU, f = -1;
        for (int n = lane; n < cN; n += 32)
            if (node_W[n * cW + w] != 0.f) f = n;
#pragma unroll
        for (int o = 16; o; o >>= 1) f = max(f, __shfl_xor_sync(0xffffffffu, f, o));
        if (lane == 0) __stcg(&g_widx[w], f);
    } else if (gw == cU + cW) {
        float a = 0.f;
        for (int n = lane; n < cN; n += 32) a += Pd[n];
        for (int w = lane; w < cW; w += 32) a -= w_exp[w];
        a = wallred(a);
        if (lane == 0) stcg(&g_beq1, a);
    } else if (gw > cU + cW && gw <= cU + cW + cS) {
        int s = gw - (cU + cW + 1);
        float a = 0.f;
        for (int w = lane; w < cW; w += 32) a += w_scen[s * cW + w];
        a = wallred(a);
        if (lane == 0) stcg(&g_beq2[s], -a);
    }
    gsync(++rnd);

    // ---- setup 2: materialize matrices, rhs vectors, init power-iter state ----
    for (int i = tid; i < cL * cU; i += NTH) {
        int l = i / cU, u = i - l * cU;
        float v = PTDF[l * cN + __ldcg(&g_gidx[u])];
        g_Hg[l * cU + u] = v;
        g_HgT[u * cL + l] = v;
    }
    for (int i = tid; i < cN * cL; i += NTH) {
        int n = i >> 9, l = i & (cL - 1);
        g_PTT[i] = PTDF[l * cN + n];
    }
    if (gw < cL) {
        int l = gw;
        const float* pr = PTDF + l * cN;
        float a = 0.f;
        for (int n = lane; n < cN; n += 32) a -= pr[n] * Pd[n];
        float hw0 = pr[__ldcg(&g_widx[lane])];
        float hw1 = pr[__ldcg(&g_widx[lane + 32])];
        a += hw0 * w_exp[lane] + hw1 * w_exp[lane + 32];
        float cf = wallred(a);
        float cap = Cap[l];
        float c3 = cap - cf, c4 = cap + cf;
        if (lane == 0) { g_c3[l] = c3; g_c4[l] = c4; }
        float bws = 0.f;
#pragma unroll 4
        for (int w = 0; w < 32; w++) {
            float h0 = __shfl_sync(0xffffffffu, hw0, w);
            float h1 = __shfl_sync(0xffffffffu, hw1, w);
            if (lane < cS)
                bws += h0 * w_scen[lane * cW + w] + h1 * w_scen[lane * cW + w + 32];
        }
        if (lane < cS) {
            g_b7[l * cS + lane] = c3 - bws;
            g_b8[l * cS + lane] = c4 + bws;
        }
    }
    // init v0 = ones + its partials (nv0 = 1, sum(p) per u-block = 2)
    for (int i = tid; i < XTOT; i += NTH) stcg(&g_X[i], 1.f);
    if (tid < NB) {
        stcg(&g_part_ss[tid], (tid == 0) ? 1.f : 0.f);
        stcg(&g_part_e[tid], 0.f);
        stcg(&g_part_p[tid], (tid < 80) ? 2.f : 0.f);
    }
    for (int i = tid; i < 80*cS; i += NTH) stcg(&g_part_c[i], 0.f);
    gsync(++rnd);

    // ---- power iteration for ||A|| (31 fused B/A pairs; norm folded into B) ----
#pragma unroll 1
    for (int it = 0; it <= NPOWER; it++) {
        phaseB<true>(blk, wId, lane, 0.f, PTDF, dsh_t, sdsh, psh, sB);
        gsync(++rnd);
        phaseA<true>(blk, wId, lane, 0.f, Cost, Cru, Crd, Pmax, sA, shp, shc, sh8, sh8b, s78s_sh);
        gsync(++rnd);
    }

    // ---- reset state + compute tau ----
    for (int i = tid; i < XTOT; i += NTH) stcg(&g_X[i], 0.f);
    for (int i = tid; i < cU; i += NTH) stcg(&g_XBP[i], 0.f);
    for (int i = tid; i < cU*cS; i += NTH) stcg(&g_XBC[i], 0.f);
    for (int i = tid; i < cN; i += NTH) stcg(&g_XBE[i], 0.f);
    for (int i = tid; i < YTOT; i += NTH) stcg(&g_Y[i], 0.f);
    for (int i = tid; i < cL * cS; i += NTH) stcg(&g_s78[i], 0.f);
    for (int i = tid; i < cL; i += NTH) { stcg(&g_s78s[i], 0.f); stcg(&g_t[i], 0.f); }
    if (tid == 0) {
        float a = 0.f;
        for (int b = 0; b < NB; b++) a += ldcg(&g_part_ss[b]);
        float Lop = sqrtf(sqrtf(a));
        stcg(&g_tau, 0.9f / Lop);
        stcg(&g_z1, 0.f); stcg(&g_z2sum, 0.f);
    }
    if (tid < cS) stcg(&g_z2[tid], 0.f);
    gsync(++rnd);

    const float tau = ldcg(&g_tau);

    // ---- PDHG main loop ----
#pragma unroll 1
    for (int it = 0; it < NITERS; it++) {
        phaseA<false>(blk, wId, lane, tau, Cost, Cru, Crd, Pmax, sA, shp, shc, sh8, sh8b, s78s_sh);
        gsync(++rnd);
        phaseB<false>(blk, wId, lane, tau, PTDF, dsh_t, sdsh, psh, sB);
        gsync(++rnd);
    }

    // ---- output ----
    if (blk < 128 && wId < 4) {
        int l = blk*4 + wId;
        const float* hr = g_Hg + (size_t)l * cU;
        float a = 0.f;
        for (int u = lane; u < cU; u += 32) a = fmaf(hr[u], ldcg(&g_X[OX_P + u]), a);
        a = wallred(a);
        if (lane == 0) {
            out[5600 + l] = g_c3[l] - a;   // f_up = Cap - flow
            out[6112 + l] = g_c4[l] + a;   // f_down = Cap + flow
        }
    } else if ((blk < 128 && wId == 4) || (blk < 32 && wId == 5)) {
        int u = (wId == 4) ? blk : (128 + blk);
        if (lane == 0) {
            out[u]       = ldcg(&g_X[OX_P + u]);
            out[160 + u] = ldcg(&g_X[OX_RU + u]);
            out[320 + u] = ldcg(&g_X[OX_RD + u]);
        }
        if (lane < cS) {
            out[480 + u*cS + lane]  = ldcg(&g_X[OX_PU + u*cS + lane]);
            out[3040 + u*cS + lane] = ldcg(&g_X[OX_PD + u*cS + lane]);
        }
    } else if (blk == 131 && wId == 7) {
        float a = 0.f;
        for (int i = lane; i < cU; i += 32)
            a += Cost[i] * ldcg(&g_X[OX_P + i]) + Cru[i] * ldcg(&g_X[OX_RU + i])
               + Crd[i] * ldcg(&g_X[OX_RD + i]);
        for (int i = lane; i < cN; i += 32)
            a += CVIOL * (ldcg(&g_X[OX_SU + i]) + ldcg(&g_X[OX_SD + i]));
        a = wallred(a);
        if (lane == 0) out[6624] = a;
    }

    // persist the barrier epoch for the next (stream-ordered) launch
    if (blk == 0 && threadIdx.x == 0) {
        asm volatile("st.global.cg.u32 [%0], %1;" :: "l"(&g_epoch), "r"(rnd) : "memory");
    }
}

extern "C" void kernel_launch(void* const* d_in, const int* in_sizes, int n_in,
                              void* d_out, int out_size) {
    const float* w_scen = (const float*)d_in[0];
    const float* Pmax   = (const float*)d_in[1];
    const float* Cost   = (const float*)d_in[2];
    const float* Cru    = (const float*)d_in[3];
    const float* Crd    = (const float*)d_in[4];
    const float* PTDF   = (const float*)d_in[5];
    const float* node_G = (const float*)d_in[6];
    const float* node_W = (const float*)d_in[7];
    // d_in[8] = node_L (identity, unused)
    const float* Pd     = (const float*)d_in[9];
    const float* w_exp  = (const float*)d_in[10];
    const float* Cap    = (const float*)d_in[11];
    float* out = (float*)d_out;
    (void)in_sizes; (void)n_in; (void)out_size;

    opf_kernel<<<NB, NT>>>(w_scen, Pmax, Cost, Cru, Crd, PTDF,
                           node_G, node_W, Pd, w_exp, Cap, out);
}

// round 10
// speedup vs baseline: 1.0077x; 1.0077x over previous
#include <cuda_runtime.h>
#include <math.h>

// ---------------- problem constants ----------------
#define cU 160
#define cL 512
#define cN 400
#define cS 16
#define cW 64
#define CVIOL 20000.0f
#define NITERS 500
#define NPOWER 30

// ---------------- grid constants ----------------
#define NB 132
#define NT 256
#define NTH (NB*NT)

// ---------------- X (primal) layout ----------------
#define OX_P   0
#define OX_RU  160
#define OX_RD  320
#define OX_PU  480
#define OX_PD  3040
#define OX_SU  5600
#define OX_SD  6000
#define XTOT   6400

// ---------------- Y (dual ineq) layout ----------------
#define OY1 0
#define OY2 160
#define OY3 320
#define OY4 832
#define OY5 1344
#define OY6 3904
#define OY7 6464
#define OY8 14656
#define YTOT 22848

// ---------------- device state (mutable: ALWAYS accessed via .cg) ----------------
__device__ __align__(16) float g_X[XTOT];
__device__ __align__(16) float g_XBP[cU];        // xbar p
__device__ __align__(16) float g_XBC[cU*cS];     // xbar (pu - pd)
__device__ __align__(16) float g_XBE[cN];        // xbar (su - sd)
__device__ __align__(16) float g_Y[YTOT];
__device__ __align__(16) float g_s78[cL*cS];
__device__ float g_s78s[cL];
__device__ float g_t[cL];
__device__ float g_z1, g_z2[cS], g_z2sum, g_tau;
__device__ float g_part_p[NB], g_part_e[NB], g_part_c[80*cS], g_part_ss[NB];

// immutable after setup (normal loads -> L1-cached)
__device__ float g_Hg[cL*cU];
__device__ float g_HgT[cU*cL];
__device__ float g_PTT[cN*cL];
__device__ float g_c3[cL], g_c4[cL];
__device__ __align__(16) float g_b7[cL*cS];
__device__ __align__(16) float g_b8[cL*cS];
__device__ int   g_gidx[cU];
__device__ int   g_widx[cW];
__device__ float g_beq1, g_beq2[cS];

// ---------------- barrier state ----------------
__device__ unsigned g_arrive[NB*8];   // stride-8 padded arrival slots
__device__ unsigned g_epoch = 0;      // persistent round base across launches

// ---------------- cg helpers ----------------
__device__ __forceinline__ float  ldcg (const float*  p){ return __ldcg(p); }
__device__ __forceinline__ float4 ldcg4(const float4* p){ return __ldcg(p); }
__device__ __forceinline__ void   stcg (float* p, float v){ __stcg(p, v); }

// ---------------- flat-arrival grid barrier (no atomics, no L1 flush) ----------------
__device__ __forceinline__ void gsync(unsigned rnd) {
    __syncthreads();
    if (threadIdx.x < 32) {
        const int lane = threadIdx.x;
        if (lane == 0) {
            asm volatile("st.release.gpu.global.u32 [%0], %1;"
                         :: "l"(&g_arrive[blockIdx.x * 8]), "r"(rnd) : "memory");
        }
        const unsigned* p0 = &g_arrive[(lane)              * 8];
        const unsigned* p1 = &g_arrive[(lane + 32)         * 8];
        const unsigned* p2 = &g_arrive[(lane + 64)         * 8];
        const unsigned* p3 = &g_arrive[(lane + 96)         * 8];
        const unsigned* p4 = &g_arrive[(128 + (lane & 3))  * 8];
        for (;;) {
            unsigned a, b, c, d, e;
            asm volatile("ld.acquire.gpu.global.u32 %0, [%1];" : "=r"(a) : "l"(p0) : "memory");
            asm volatile("ld.acquire.gpu.global.u32 %0, [%1];" : "=r"(b) : "l"(p1) : "memory");
            asm volatile("ld.acquire.gpu.global.u32 %0, [%1];" : "=r"(c) : "l"(p2) : "memory");
            asm volatile("ld.acquire.gpu.global.u32 %0, [%1];" : "=r"(d) : "l"(p3) : "memory");
            asm volatile("ld.acquire.gpu.global.u32 %0, [%1];" : "=r"(e) : "l"(p4) : "memory");
            bool ok = ((int)(a - rnd) >= 0) && ((int)(b - rnd) >= 0) &&
                      ((int)(c - rnd) >= 0) && ((int)(d - rnd) >= 0) &&
                      ((int)(e - rnd) >= 0);
            if (__all_sync(0xffffffffu, ok)) break;
            __nanosleep(40);
        }
    }
    __syncthreads();
}

// ---------------- warp helpers ----------------
__device__ __forceinline__ float wallred(float v) {
#pragma unroll
    for (int o = 16; o; o >>= 1) v += __shfl_xor_sync(0xffffffffu, v, o);
    return v;
}

__device__ __forceinline__ void allred16(float (&v)[16]) {
#pragma unroll
    for (int o = 16; o; o >>= 1) {
#pragma unroll
        for (int k = 0; k < 16; k++) v[k] += __shfl_xor_sync(0xffffffffu, v[k], o);
    }
}

__device__ __forceinline__ float pick16(const float (&a)[16], int s) {
    float r = a[0];
#pragma unroll
    for (int k = 1; k < 16; k++) r = (s == k) ? a[k] : r;
    return r;
}

__device__ __forceinline__ void fma16cg(float (&acc)[16], float h, const float4* p) {
    float4 a0 = __ldcg(p), a1 = __ldcg(p+1), a2 = __ldcg(p+2), a3 = __ldcg(p+3);
    acc[0]  = fmaf(h, a0.x, acc[0]);  acc[1]  = fmaf(h, a0.y, acc[1]);
    acc[2]  = fmaf(h, a0.z, acc[2]);  acc[3]  = fmaf(h, a0.w, acc[3]);
    acc[4]  = fmaf(h, a1.x, acc[4]);  acc[5]  = fmaf(h, a1.y, acc[5]);
    acc[6]  = fmaf(h, a1.z, acc[6]);  acc[7]  = fmaf(h, a1.w, acc[7]);
    acc[8]  = fmaf(h, a2.x, acc[8]);  acc[9]  = fmaf(h, a2.y, acc[9]);
    acc[10] = fmaf(h, a2.z, acc[10]); acc[11] = fmaf(h, a2.w, acc[11]);
    acc[12] = fmaf(h, a3.x, acc[12]); acc[13] = fmaf(h, a3.y, acc[13]);
    acc[14] = fmaf(h, a3.z, acc[14]); acc[15] = fmaf(h, a3.w, acc[15]);
}

// transposed smem read: dsh_t[k*160 + u], lane-consecutive u -> conflict-free LDS.32
__device__ __forceinline__ void fma16sh_t(float (&acc)[16], float h, const float* base_u) {
#pragma unroll
    for (int k = 0; k < 16; k++) acc[k] = fmaf(h, base_u[k * cU], acc[k]);
}

// ---------------- Phase A ----------------
// u-part: blocks 0..79 (2 u/block, 4 warps/u); n-part: blocks 80..131 (<=1 row/warp).
// Non-POW also applies the fused y1/y2/y5/y6 dual updates and writes packed xbar arrays.
template<bool POW>
__device__ __forceinline__ void phaseA(int blk, int wId, int lane, float tau,
                                       const float* __restrict__ Cost,
                                       const float* __restrict__ Cru,
                                       const float* __restrict__ Crd,
                                       const float* __restrict__ Pmax,
                                       float* sA, float* shp, float* shc,
                                       float* sh8, float* sh8b, float* s78s_sh)
{
    const float sig = tau;
    if (blk < 80) {
        const int u  = 2*blk + (wId >> 2);
        const int Lb = (wId & 3) * 128;
        const bool comb = ((wId & 3) == 0);
        // prefetch duals before the dot (latency hidden under FMAs)
        float y5v = 0.f, y6v = 0.f, y1u = 0.f, y2u = 0.f, z1 = 0.f, z2s = 0.f;
        if (comb) {
            if (lane < cS) {
                y5v = ldcg(&g_Y[OY5 + u*cS + lane]);
                y6v = ldcg(&g_Y[OY6 + u*cS + lane]);
                z2s = ldcg(&g_z2[lane]);
            }
            y1u = ldcg(&g_Y[OY1 + u]); y2u = ldcg(&g_Y[OY2 + u]);
            z1  = ldcg(&g_z1);
        }
        float accT = 0.f;
        float acc[16];
#pragma unroll
        for (int k = 0; k < 16; k++) acc[k] = 0.f;
        const float* hr = g_HgT + (size_t)u * cL + Lb;
#pragma unroll
        for (int j = 0; j < 4; j++) {
            int l = lane + 32*j;
            float h = hr[l];                              // L1-cached
            accT = fmaf(h, ldcg(&g_t[Lb + l]), accT);
            fma16cg(acc, h, reinterpret_cast<const float4*>(g_s78 + (size_t)(Lb + l) * cS));
        }
        accT = wallred(accT);
        allred16(acc);
        if (lane < 16) sA[wId*17 + lane] = pick16(acc, lane);
        if (lane == 0) sA[wId*17 + 16] = accT;
        __syncthreads();
        if (comb) {
            const int half = wId >> 2;
            const int b0 = (half*4) * 17;
            float aT = sA[b0+16] + sA[b0+17+16] + sA[b0+34+16] + sA[b0+51+16];
            float aS = 0.f;
            if (lane < 16) aS = sA[b0+lane] + sA[b0+17+lane] + sA[b0+34+lane] + sA[b0+51+lane];
            float sum5 = wallred((lane < cS) ? y5v : 0.f);
            float sum6 = wallred((lane < cS) ? y6v : 0.f);
            float ssv = 0.f;
            float xb_p = 0.f, xb_ru = 0.f, xb_rd = 0.f;
            if (lane == 0) {
                float gp  = y1u - y2u + aT + z1;
                float gru = y1u - sum5;
                float grd = y2u - sum6;
                if (POW) {
                    stcg(&g_X[OX_P + u], gp); stcg(&g_X[OX_RU + u], gru); stcg(&g_X[OX_RD + u], grd);
                    ssv += gp*gp + gru*gru + grd*grd;
                    shp[half] = gp;
                } else {
                    float x = ldcg(&g_X[OX_P + u]);
                    float xn = fmaxf(x - tau*(Cost[u] + gp), 0.f);
                    xb_p = 2.f*xn - x;
                    stcg(&g_X[OX_P + u], xn); stcg(&g_XBP[u], xb_p); shp[half] = xb_p;
                    x = ldcg(&g_X[OX_RU + u]); xn = fmaxf(x - tau*(Cru[u] + gru), 0.f);
                    xb_ru = 2.f*xn - x;
                    stcg(&g_X[OX_RU + u], xn);
                    x = ldcg(&g_X[OX_RD + u]); xn = fmaxf(x - tau*(Crd[u] + grd), 0.f);
                    xb_rd = 2.f*xn - x;
                    stcg(&g_X[OX_RD + u], xn);
                }
            }
            if (!POW) {
                xb_ru = __shfl_sync(0xffffffffu, xb_ru, 0);
                xb_rd = __shfl_sync(0xffffffffu, xb_rd, 0);
            }
            if (lane < cS) {
                float gpu_ = y5v + aS + z2s;
                float gpd_ = y6v - aS - z2s;
                int iu = OX_PU + u*cS + lane, id = OX_PD + u*cS + lane;
                if (POW) {
                    stcg(&g_X[iu], gpu_); stcg(&g_X[id], gpd_);
                    ssv += gpu_*gpu_ + gpd_*gpd_;
                    shc[half*cS + lane] = gpu_ - gpd_;
                } else {
                    float x = ldcg(&g_X[iu]); float xn = fmaxf(x - tau*gpu_, 0.f);
                    float xbu = 2.f*xn - x; stcg(&g_X[iu], xn);
                    x = ldcg(&g_X[id]); xn = fmaxf(x - tau*gpd_, 0.f);
                    float xbd = 2.f*xn - x; stcg(&g_X[id], xn);
                    stcg(&g_XBC[u*cS + lane], xbu - xbd);
                    shc[half*cS + lane] = xbu - xbd;
                    float y5n = fmaxf(y5v + sig*(xbu - xb_ru), 0.f);
                    float y6n = fmaxf(y6v + sig*(xbd - xb_rd), 0.f);
                    stcg(&g_Y[OY5 + u*cS + lane], y5n);
                    stcg(&g_Y[OY6 + u*cS + lane], y6n);
                }
            }
            if (!POW && lane == 0) {
                float y1n = fmaxf(y1u + sig*(xb_p + xb_ru - Pmax[u]), 0.f);
                float y2n = fmaxf(y2u + sig*(xb_rd - xb_p), 0.f);
                stcg(&g_Y[OY1 + u], y1n); stcg(&g_Y[OY2 + u], y2n);
            }
            if (POW) {
                float w = wallred(ssv);
                if (lane == 0) sh8[half] = w;
            }
        }
        __syncthreads();
        if (wId == 0) {
            if (lane == 0) stcg(&g_part_p[blk], shp[0] + shp[1]);
            if (lane < cS) stcg(&g_part_c[blk*cS + lane], shc[lane] + shc[cS + lane]);
            if (POW && lane == 0) stcg(&g_part_ss[blk], sh8[0] + sh8[1]);
        }
    } else {
        for (int i = threadIdx.x; i < cL; i += NT) s78s_sh[i] = ldcg(&g_s78s[i]);
        __syncthreads();
        const int wn = (blk - 80)*8 + wId;   // 0..415, active < 400
        float agg_e = 0.f, agg_ss = 0.f;
        if (wn < cN) {
            float zs = ldcg(&g_z2sum);
            float a0 = 0.f;
            const float* r0 = g_PTT + (size_t)wn * cL;
#pragma unroll 4
            for (int l = lane; l < cL; l += 32) a0 = fmaf(r0[l], s78s_sh[l], a0);
            a0 = wallred(a0);
            if (lane == 0) {
                float gsu = a0 + zs, gsd = -a0 - zs;
                if (POW) {
                    stcg(&g_X[OX_SU + wn], gsu); stcg(&g_X[OX_SD + wn], gsd);
                    agg_ss = gsu*gsu + gsd*gsd;
                    agg_e  = gsu - gsd;
                } else {
                    float x = ldcg(&g_X[OX_SU + wn]); float xn = fmaxf(x - tau*(CVIOL + gsu), 0.f);
                    float xbu = 2.f*xn - x; stcg(&g_X[OX_SU + wn], xn);
                    x = ldcg(&g_X[OX_SD + wn]); xn = fmaxf(x - tau*(CVIOL + gsd), 0.f);
                    float xbd = 2.f*xn - x; stcg(&g_X[OX_SD + wn], xn);
                    stcg(&g_XBE[wn], xbu - xbd);
                    agg_e = xbu - xbd;
                }
            }
        }
        if (lane == 0) { sh8[wId] = agg_e; sh8b[wId] = agg_ss; }
        __syncthreads();
        if (wId == 0 && lane == 0) {
            float se = 0.f, ss = 0.f;
#pragma unroll
            for (int k = 0; k < 8; k++) { se += sh8[k]; ss += sh8b[k]; }
            stcg(&g_part_e[blk], se);
            if (POW) stcg(&g_part_ss[blk], ss);
        }
    }
}

// ---------------- Phase B ----------------
// l-part: blocks 0..127, 4 l/block, 2 warps per l (u/n halves, smem combine).
// POW: blocks 128..131 write u-y rows (scaled); eq-duals: block 128 warp 7.
template<bool POW>
__device__ __forceinline__ void phaseB(int blk, int wId, int lane, float sig,
                                       const float* __restrict__ PTDF,
                                       float* dsh_t, float* sdsh, float* psh, float* sB)
{
    float inv = 1.f;
    if (POW) {
        float a = 0.f;
#pragma unroll
        for (int k = 0; k < 4; k++) a += ldcg(&g_part_ss[lane + 32*k]);
        if (lane < 4) a += ldcg(&g_part_ss[128 + lane]);
        a = wallred(a);
        inv = rsqrtf(a);
    }
    if (blk < 128) {
        // ---- staging ----
        if (POW) {
            for (int c = threadIdx.x; c < (cU*cS/4); c += NT) {
                float4 a = ldcg4(reinterpret_cast<const float4*>(g_X + OX_PU) + c);
                float4 b = ldcg4(reinterpret_cast<const float4*>(g_X + OX_PD) + c);
                int u = c >> 2, s0 = (c & 3) * 4;
                dsh_t[(s0+0)*cU + u] = (a.x - b.x) * inv;
                dsh_t[(s0+1)*cU + u] = (a.y - b.y) * inv;
                dsh_t[(s0+2)*cU + u] = (a.z - b.z) * inv;
                dsh_t[(s0+3)*cU + u] = (a.w - b.w) * inv;
            }
            for (int i = threadIdx.x; i < cN; i += NT)
                sdsh[i] = (ldcg(&g_X[OX_SU + i]) - ldcg(&g_X[OX_SD + i])) * inv;
            for (int i = threadIdx.x; i < cU; i += NT)
                psh[i] = ldcg(&g_X[OX_P + i]) * inv;
        } else {
            for (int c = threadIdx.x; c < (cU*cS/4); c += NT) {
                float4 d = ldcg4(reinterpret_cast<const float4*>(g_XBC) + c);
                int u = c >> 2, s0 = (c & 3) * 4;
                dsh_t[(s0+0)*cU + u] = d.x;
                dsh_t[(s0+1)*cU + u] = d.y;
                dsh_t[(s0+2)*cU + u] = d.z;
                dsh_t[(s0+3)*cU + u] = d.w;
            }
            for (int i = threadIdx.x; i < cN; i += NT) sdsh[i] = ldcg(&g_XBE[i]);
            for (int i = threadIdx.x; i < cU; i += NT) psh[i] = ldcg(&g_XBP[i]);
        }
        __syncthreads();
        const int l = blk*4 + (wId >> 1);
        const int half = wId & 1;
        // prefetch duals on the combining (half==0) warp
        float y3 = 0.f, y4 = 0.f, y7 = 0.f, y8 = 0.f;
        if (!POW && half == 0) {
            y3 = ldcg(&g_Y[OY3 + l]);
            y4 = ldcg(&g_Y[OY4 + l]);
            if (lane < cS) {
                y7 = ldcg(&g_Y[OY7 + l*cS + lane]);
                y8 = ldcg(&g_Y[OY8 + l*cS + lane]);
            }
        }
        float accF = 0.f, accP = 0.f;
        float acc[16];
#pragma unroll
        for (int k = 0; k < 16; k++) acc[k] = 0.f;
        const float* hr = g_Hg + (size_t)l * cU;
        const int u0 = half * 80;
        for (int u = u0 + lane; u < u0 + 80; u += 32) {
            float h = hr[u];
            accF = fmaf(h, psh[u], accF);
            fma16sh_t(acc, h, dsh_t + u);
        }
        const float* pr = PTDF + (size_t)l * cN;
        const int n0 = half * 200;
#pragma unroll 2
        for (int n = n0 + lane; n < n0 + 200; n += 32) accP = fmaf(pr[n], sdsh[n], accP);
        accF = wallred(accF);
        accP = wallred(accP);
        allred16(acc);
        if (lane < 16) sB[wId*19 + lane] = pick16(acc, lane);
        if (lane == 0) { sB[wId*19 + 16] = accF; sB[wId*19 + 17] = accP; }
        __syncthreads();
        if (half == 0) {
            float fp = sB[wId*19 + 16] + sB[(wId+1)*19 + 16];
            float aP = sB[wId*19 + 17] + sB[(wId+1)*19 + 17];
            float aS = (lane < 16) ? (sB[wId*19 + lane] + sB[(wId+1)*19 + lane]) : 0.f;
            float base = fp + aP;
            float y3n, y4n;
            if (POW) { y3n = fp; y4n = -fp; }
            else {
                y3n = fmaxf(y3 + sig*( fp - g_c3[l]), 0.f);
                y4n = fmaxf(y4 + sig*(-fp - g_c4[l]), 0.f);
            }
            float s78v = 0.f;
            if (lane < cS) {
                float scen = aS + base;
                float y7n, y8n;
                if (POW) { y7n = scen; y8n = -scen; }
                else {
                    y7n = fmaxf(y7 + sig*( scen - g_b7[l*cS + lane]), 0.f);
                    y8n = fmaxf(y8 + sig*(-scen - g_b8[l*cS + lane]), 0.f);
                }
                stcg(&g_Y[OY7 + l*cS + lane], y7n);
                stcg(&g_Y[OY8 + l*cS + lane], y8n);
                s78v = y7n - y8n;
                stcg(&g_s78[l*cS + lane], s78v);
            }
            float s78s = wallred(s78v);
            if (lane == 0) {
                stcg(&g_Y[OY3 + l], y3n);
                stcg(&g_Y[OY4 + l], y4n);
                stcg(&g_s78s[l], s78s);
                stcg(&g_t[l], y3n - y4n + s78s);
            }
        }
    } else {
        if (POW) {
            const int base = (blk - 128)*40 + wId*5;
#pragma unroll
            for (int r = 0; r < 5; r++) {
                const int u = base + r;
                float ru = ldcg(&g_X[OX_RU + u]) * inv;
                float rd = ldcg(&g_X[OX_RD + u]) * inv;
                if (lane == 0) {
                    float p = ldcg(&g_X[OX_P + u]) * inv;
                    stcg(&g_Y[OY1 + u], p + ru);
                    stcg(&g_Y[OY2 + u], rd - p);
                }
                if (lane < cS) {
                    float pu = ldcg(&g_X[OX_PU + u*cS + lane]) * inv;
                    float pd = ldcg(&g_X[OX_PD + u*cS + lane]) * inv;
                    stcg(&g_Y[OY5 + u*cS + lane], pu - ru);
                    stcg(&g_Y[OY6 + u*cS + lane], pd - rd);
                }
            }
        }
        if (blk == 128 && wId == 7) {
            float sp = 0.f;
            for (int b = lane; b < 80; b += 32) sp += ldcg(&g_part_p[b]);
            sp = wallred(sp);
            float se = 0.f;
            for (int b = 80 + lane; b < NB; b += 32) se += ldcg(&g_part_e[b]);
            se = wallred(se);
            int s = lane & 15, h = lane >> 4;
            float sc = 0.f;
#pragma unroll
            for (int b = h*40; b < h*40 + 40; b++) sc += ldcg(&g_part_c[b*cS + s]);
            sc += __shfl_xor_sync(0xffffffffu, sc, 16);
            float ae2 = sc + se;
            float z2n = 0.f;
            if (lane < cS) {
                z2n = POW ? (ae2 * inv) : (ldcg(&g_z2[lane]) + sig*(ae2 - g_beq2[lane]));
                stcg(&g_z2[lane], z2n);
            }
            float zs = wallred((lane < cS) ? z2n : 0.f);
            if (lane == 0) {
                float z1n = POW ? (sp * inv) : (ldcg(&g_z1) + sig*(sp - g_beq1));
                stcg(&g_z1, z1n);
                stcg(&g_z2sum, zs);
            }
        }
    }
}

// ---------------- main persistent kernel ----------------
__global__ void __launch_bounds__(NT, 1)
opf_kernel(const float* __restrict__ w_scen, const float* __restrict__ Pmax,
           const float* __restrict__ Cost, const float* __restrict__ Cru,
           const float* __restrict__ Crd, const float* __restrict__ PTDF,
           const float* __restrict__ node_G, const float* __restrict__ node_W,
           const float* __restrict__ Pd, const float* __restrict__ w_exp,
           const float* __restrict__ Cap, float* __restrict__ out)
{
    __shared__ __align__(16) float dsh_t[cS*cU];
    __shared__ float sdsh[cN];
    __shared__ float psh[cU];
    __shared__ float s78s_sh[cL];
    __shared__ float sA[8*17];
    __shared__ float sB[8*19];
    __shared__ float shp[2], shc[2*cS], sh8[8], sh8b[8];

    const int blk  = blockIdx.x;
    const int tid  = blk * NT + threadIdx.x;
    const int wId  = threadIdx.x >> 5;
    const int lane = threadIdx.x & 31;
    const int gw   = blk * 8 + wId;
    unsigned rnd;
    {
        unsigned e;
        asm volatile("ld.global.cg.u32 %0, [%1];" : "=r"(e) : "l"(&g_epoch));
        rnd = e;
    }

    // ---- setup 1: index extraction + equality rhs ----
    if (gw < cU) {
        int u = gw, f = -1;
        for (int n = lane; n < cN; n += 32)
            if (node_G[n * cU + u] != 0.f) f = n;
#pragma unroll
        for (int o = 16; o; o >>= 1) f = max(f, __shfl_xor_sync(0xffffffffu, f, o));
        if (lane == 0) __stcg(&g_gidx[u], f);
    } else if (gw < cU + cW) {
        int w = gw - cU, f = -1;
        for (int n = lane; n < cN; n += 32)
            if (node_W[n * cW + w] != 0.f) f = n;
#pragma unroll
        for (int o = 16; o; o >>= 1) f = max(f, __shfl_xor_sync(0xffffffffu, f, o));
        if (lane == 0) __stcg(&g_widx[w], f);
    } else if (gw == cU + cW) {
        float a = 0.f;
        for (int n = lane; n < cN; n += 32) a += Pd[n];
        for (int w = lane; w < cW; w += 32) a -= w_exp[w];
        a = wallred(a);
        if (lane == 0) stcg(&g_beq1, a);
    } else if (gw > cU + cW && gw <= cU + cW + cS) {
        int s = gw - (cU + cW + 1);
        float a = 0.f;
        for (int w = lane; w < cW; w += 32) a += w_scen[s * cW + w];
        a = wallred(a);
        if (lane == 0) stcg(&g_beq2[s], -a);
    }
    gsync(++rnd);

    // ---- setup 2: materialize matrices, rhs vectors, init power-iter state ----
    for (int i = tid; i < cL * cU; i += NTH) {
        int l = i / cU, u = i - l * cU;
        float v = PTDF[l * cN + __ldcg(&g_gidx[u])];
        g_Hg[l * cU + u] = v;
        g_HgT[u * cL + l] = v;
    }
    for (int i = tid; i < cN * cL; i += NTH) {
        int n = i >> 9, l = i & (cL - 1);
        g_PTT[i] = PTDF[l * cN + n];
    }
    if (gw < cL) {
        int l = gw;
        const float* pr = PTDF + l * cN;
        float a = 0.f;
        for (int n = lane; n < cN; n += 32) a -= pr[n] * Pd[n];
        float hw0 = pr[__ldcg(&g_widx[lane])];
        float hw1 = pr[__ldcg(&g_widx[lane + 32])];
        a += hw0 * w_exp[lane] + hw1 * w_exp[lane + 32];
        float cf = wallred(a);
        float cap = Cap[l];
        float c3 = cap - cf, c4 = cap + cf;
        if (lane == 0) { g_c3[l] = c3; g_c4[l] = c4; }
        float bws = 0.f;
#pragma unroll 4
        for (int w = 0; w < 32; w++) {
            float h0 = __shfl_sync(0xffffffffu, hw0, w);
            float h1 = __shfl_sync(0xffffffffu, hw1, w);
            if (lane < cS)
                bws += h0 * w_scen[lane * cW + w] + h1 * w_scen[lane * cW + w + 32];
        }
        if (lane < cS) {
            g_b7[l * cS + lane] = c3 - bws;
            g_b8[l * cS + lane] = c4 + bws;
        }
    }
    // init v0 = ones + its partials (nv0 = 1, sum(p) per u-block = 2)
    for (int i = tid; i < XTOT; i += NTH) stcg(&g_X[i], 1.f);
    if (tid < NB) {
        stcg(&g_part_ss[tid], (tid == 0) ? 1.f : 0.f);
        stcg(&g_part_e[tid], 0.f);
        stcg(&g_part_p[tid], (tid < 80) ? 2.f : 0.f);
    }
    for (int i = tid; i < 80*cS; i += NTH) stcg(&g_part_c[i], 0.f);
    gsync(++rnd);

    // ---- power iteration for ||A|| (31 fused B/A pairs; norm folded into B) ----
#pragma unroll 1
    for (int it = 0; it <= NPOWER; it++) {
        phaseB<true>(blk, wId, lane, 0.f, PTDF, dsh_t, sdsh, psh, sB);
        gsync(++rnd);
        phaseA<true>(blk, wId, lane, 0.f, Cost, Cru, Crd, Pmax, sA, shp, shc, sh8, sh8b, s78s_sh);
        gsync(++rnd);
    }

    // ---- reset state + compute tau ----
    for (int i = tid; i < XTOT; i += NTH) stcg(&g_X[i], 0.f);
    for (int i = tid; i < cU; i += NTH) stcg(&g_XBP[i], 0.f);
    for (int i = tid; i < cU*cS; i += NTH) stcg(&g_XBC[i], 0.f);
    for (int i = tid; i < cN; i += NTH) stcg(&g_XBE[i], 0.f);
    for (int i = tid; i < YTOT; i += NTH) stcg(&g_Y[i], 0.f);
    for (int i = tid; i < cL * cS; i += NTH) stcg(&g_s78[i], 0.f);
    for (int i = tid; i < cL; i += NTH) { stcg(&g_s78s[i], 0.f); stcg(&g_t[i], 0.f); }
    if (tid == 0) {
        float a = 0.f;
        for (int b = 0; b < NB; b++) a += ldcg(&g_part_ss[b]);
        float Lop = sqrtf(sqrtf(a));
        stcg(&g_tau, 0.9f / Lop);
        stcg(&g_z1, 0.f); stcg(&g_z2sum, 0.f);
    }
    if (tid < cS) stcg(&g_z2[tid], 0.f);
    gsync(++rnd);

    const float tau = ldcg(&g_tau);

    // ---- PDHG main loop ----
#pragma unroll 1
    for (int it = 0; it < NITERS; it++) {
        phaseA<false>(blk, wId, lane, tau, Cost, Cru, Crd, Pmax, sA, shp, shc, sh8, sh8b, s78s_sh);
        gsync(++rnd);
        phaseB<false>(blk, wId, lane, tau, PTDF, dsh_t, sdsh, psh, sB);
        gsync(++rnd);
    }

    // ---- output ----
    if (blk < 128 && wId < 4) {
        int l = blk*4 + wId;
        const float* hr = g_Hg + (size_t)l * cU;
        float a = 0.f;
        for (int u = lane; u < cU; u += 32) a = fmaf(hr[u], ldcg(&g_X[OX_P + u]), a);
        a = wallred(a);
        if (lane == 0) {
            out[5600 + l] = g_c3[l] - a;   // f_up = Cap - flow
            out[6112 + l] = g_c4[l] + a;   // f_down = Cap + flow
        }
    } else if ((blk < 128 && wId == 4) || (blk < 32 && wId == 5)) {
        int u = (wId == 4) ? blk : (128 + blk);
        if (lane == 0) {
            out[u]       = ldcg(&g_X[OX_P + u]);
            out[160 + u] = ldcg(&g_X[OX_RU + u]);
            out[320 + u] = ldcg(&g_X[OX_RD + u]);
        }
        if (lane < cS) {
            out[480 + u*cS + lane]  = ldcg(&g_X[OX_PU + u*cS + lane]);
            out[3040 + u*cS + lane] = ldcg(&g_X[OX_PD + u*cS + lane]);
        }
    } else if (blk == 131 && wId == 7) {
        float a = 0.f;
        for (int i = lane; i < cU; i += 32)
            a += Cost[i] * ldcg(&g_X[OX_P + i]) + Cru[i] * ldcg(&g_X[OX_RU + i])
               + Crd[i] * ldcg(&g_X[OX_RD + i]);
        for (int i = lane; i < cN; i += 32)
            a += CVIOL * (ldcg(&g_X[OX_SU + i]) + ldcg(&g_X[OX_SD + i]));
        a = wallred(a);
        if (lane == 0) out[6624] = a;
    }

    // persist the barrier epoch for the next (stream-ordered) launch
    if (blk == 0 && threadIdx.x == 0) {
        asm volatile("st.global.cg.u32 [%0], %1;" :: "l"(&g_epoch), "r"(rnd) : "memory");
    }
}

extern "C" void kernel_launch(void* const* d_in, const int* in_sizes, int n_in,
                              void* d_out, int out_size) {
    const float* w_scen = (const float*)d_in[0];
    const float* Pmax   = (const float*)d_in[1];
    const float* Cost   = (const float*)d_in[2];
    const float* Cru    = (const float*)d_in[3];
    const float* Crd    = (const float*)d_in[4];
    const float* PTDF   = (const float*)d_in[5];
    const float* node_G = (const float*)d_in[6];
    const float* node_W = (const float*)d_in[7];
    // d_in[8] = node_L (identity, unused)
    const float* Pd     = (const float*)d_in[9];
    const float* w_exp  = (const float*)d_in[10];
    const float* Cap    = (const float*)d_in[11];
    float* out = (float*)d_out;
    (void)in_sizes; (void)n_in; (void)out_size;

    opf_kernel<<<NB, NT>>>(w_scen, Pmax, Cost, Cru, Crd, PTDF,
                           node_G, node_W, Pd, w_exp, Cap, out);
}

// round 11
// speedup vs baseline: 1.1272x; 1.1186x over previous
#include <cuda_runtime.h>
#include <math.h>

// ---------------- problem constants ----------------
#define cU 160
#define cL 512
#define cN 400
#define cS 16
#define cW 64
#define CVIOL 20000.0f
#define NITERS 500
#define NPOWER 30

// ---------------- grid constants ----------------
#define NB 132
#define NT 256
#define NTH (NB*NT)

// ---------------- X (primal) layout ----------------
#define OX_P   0
#define OX_RU  160
#define OX_RD  320
#define OX_PU  480
#define OX_PD  3040
#define OX_SU  5600
#define OX_SD  6000
#define XTOT   6400

// ---------------- Y (dual ineq) layout ----------------
#define OY1 0
#define OY2 160
#define OY3 320
#define OY4 832
#define OY5 1344
#define OY6 3904
#define OY7 6464
#define OY8 14656
#define YTOT 22848

// ---------------- device state (mutable: ALWAYS accessed via .cg) ----------------
__device__ __align__(16) float g_X[XTOT];
__device__ __align__(16) float g_XBP[cU];        // xbar p
__device__ __align__(16) float g_XBC[cU*cS];     // xbar (pu - pd)
__device__ __align__(16) float g_XBE[cN];        // xbar (su - sd)
__device__ __align__(16) float g_Y[YTOT];
__device__ __align__(16) float g_s78[cL*cS];
__device__ float g_s78s[cL];
__device__ float g_t[cL];
__device__ float g_z1, g_z2[cS], g_z2sum, g_tau;
__device__ float g_part_p[NB], g_part_e[NB], g_part_c[80*cS], g_part_ss[NB];

// immutable after setup (normal loads -> L1-cached)
__device__ float g_Hg[cL*cU];
__device__ float g_HgT[cU*cL];
__device__ float g_PTT[cN*cL];
__device__ float g_c3[cL], g_c4[cL];
__device__ __align__(16) float g_b7[cL*cS];
__device__ __align__(16) float g_b8[cL*cS];
__device__ int   g_gidx[cU];
__device__ int   g_widx[cW];
__device__ float g_beq1, g_beq2[cS];

// ---------------- barrier state ----------------
__device__ unsigned g_arrive[NB*8];   // stride-8 padded arrival slots
__device__ unsigned g_epoch = 0;      // persistent round base across launches

// ---------------- cg helpers ----------------
__device__ __forceinline__ float  ldcg (const float*  p){ return __ldcg(p); }
__device__ __forceinline__ float4 ldcg4(const float4* p){ return __ldcg(p); }
__device__ __forceinline__ void   stcg (float* p, float v){ __stcg(p, v); }

// ---------------- flat-arrival grid barrier (no atomics, no L1 flush) ----------------
__device__ __forceinline__ void gsync(unsigned rnd) {
    __syncthreads();
    if (threadIdx.x < 32) {
        const int lane = threadIdx.x;
        if (lane == 0) {
            asm volatile("st.release.gpu.global.u32 [%0], %1;"
                         :: "l"(&g_arrive[blockIdx.x * 8]), "r"(rnd) : "memory");
        }
        const unsigned* p0 = &g_arrive[(lane)              * 8];
        const unsigned* p1 = &g_arrive[(lane + 32)         * 8];
        const unsigned* p2 = &g_arrive[(lane + 64)         * 8];
        const unsigned* p3 = &g_arrive[(lane + 96)         * 8];
        const unsigned* p4 = &g_arrive[(128 + (lane & 3))  * 8];
        for (;;) {
            unsigned a, b, c, d, e;
            asm volatile("ld.acquire.gpu.global.u32 %0, [%1];" : "=r"(a) : "l"(p0) : "memory");
            asm volatile("ld.acquire.gpu.global.u32 %0, [%1];" : "=r"(b) : "l"(p1) : "memory");
            asm volatile("ld.acquire.gpu.global.u32 %0, [%1];" : "=r"(c) : "l"(p2) : "memory");
            asm volatile("ld.acquire.gpu.global.u32 %0, [%1];" : "=r"(d) : "l"(p3) : "memory");
            asm volatile("ld.acquire.gpu.global.u32 %0, [%1];" : "=r"(e) : "l"(p4) : "memory");
            bool ok = ((int)(a - rnd) >= 0) && ((int)(b - rnd) >= 0) &&
                      ((int)(c - rnd) >= 0) && ((int)(d - rnd) >= 0) &&
                      ((int)(e - rnd) >= 0);
            if (__all_sync(0xffffffffu, ok)) break;
            __nanosleep(40);
        }
    }
    __syncthreads();
}

// ---------------- warp helpers ----------------
__device__ __forceinline__ float wallred(float v) {
#pragma unroll
    for (int o = 16; o; o >>= 1) v += __shfl_xor_sync(0xffffffffu, v, o);
    return v;
}

__device__ __forceinline__ void allred16(float (&v)[16]) {
#pragma unroll
    for (int o = 16; o; o >>= 1) {
#pragma unroll
        for (int k = 0; k < 16; k++) v[k] += __shfl_xor_sync(0xffffffffu, v[k], o);
    }
}

__device__ __forceinline__ float pick16(const float (&a)[16], int s) {
    float r = a[0];
#pragma unroll
    for (int k = 1; k < 16; k++) r = (s == k) ? a[k] : r;
    return r;
}

__device__ __forceinline__ void fma16cg(float (&acc)[16], float h, const float4* p) {
    float4 a0 = __ldcg(p), a1 = __ldcg(p+1), a2 = __ldcg(p+2), a3 = __ldcg(p+3);
    acc[0]  = fmaf(h, a0.x, acc[0]);  acc[1]  = fmaf(h, a0.y, acc[1]);
    acc[2]  = fmaf(h, a0.z, acc[2]);  acc[3]  = fmaf(h, a0.w, acc[3]);
    acc[4]  = fmaf(h, a1.x, acc[4]);  acc[5]  = fmaf(h, a1.y, acc[5]);
    acc[6]  = fmaf(h, a1.z, acc[6]);  acc[7]  = fmaf(h, a1.w, acc[7]);
    acc[8]  = fmaf(h, a2.x, acc[8]);  acc[9]  = fmaf(h, a2.y, acc[9]);
    acc[10] = fmaf(h, a2.z, acc[10]); acc[11] = fmaf(h, a2.w, acc[11]);
    acc[12] = fmaf(h, a3.x, acc[12]); acc[13] = fmaf(h, a3.y, acc[13]);
    acc[14] = fmaf(h, a3.z, acc[14]); acc[15] = fmaf(h, a3.w, acc[15]);
}

// transposed smem read: dsh_t[k*160 + u], lane-consecutive u -> conflict-free LDS.32
__device__ __forceinline__ void fma16sh_t(float (&acc)[16], float h, const float* base_u) {
#pragma unroll
    for (int k = 0; k < 16; k++) acc[k] = fmaf(h, base_u[k * cU], acc[k]);
}

// ---------------- Phase A ----------------
// u-part: blocks 0..79 (2 u/block, 4 warps/u); n-part: blocks 80..131 (<=1 row/warp).
// Non-POW also applies the fused y1/y2/y5/y6 dual updates and writes packed xbar arrays.
template<bool POW>
__device__ __forceinline__ void phaseA(int blk, int wId, int lane, float tau,
                                       const float* __restrict__ Cost,
                                       const float* __restrict__ Cru,
                                       const float* __restrict__ Crd,
                                       const float* __restrict__ Pmax,
                                       float* sA, float* shp, float* shc,
                                       float* sh8, float* sh8b, float* s78s_sh)
{
    const float sig = tau;
    if (blk < 80) {
        const int u  = 2*blk + (wId >> 2);
        const int Lb = (wId & 3) * 128;
        const bool comb = ((wId & 3) == 0);
        // prefetch duals before the dot (latency hidden under FMAs)
        float y5v = 0.f, y6v = 0.f, y1u = 0.f, y2u = 0.f, z1 = 0.f, z2s = 0.f;
        if (comb) {
            if (lane < cS) {
                y5v = ldcg(&g_Y[OY5 + u*cS + lane]);
                y6v = ldcg(&g_Y[OY6 + u*cS + lane]);
                z2s = ldcg(&g_z2[lane]);
            }
            y1u = ldcg(&g_Y[OY1 + u]); y2u = ldcg(&g_Y[OY2 + u]);
            z1  = ldcg(&g_z1);
        }
        float accT = 0.f;
        float acc[16];
#pragma unroll
        for (int k = 0; k < 16; k++) acc[k] = 0.f;
        const float* hr = g_HgT + (size_t)u * cL + Lb;
#pragma unroll
        for (int j = 0; j < 4; j++) {
            int l = lane + 32*j;
            float h = hr[l];                              // L1-cached
            accT = fmaf(h, ldcg(&g_t[Lb + l]), accT);
            fma16cg(acc, h, reinterpret_cast<const float4*>(g_s78 + (size_t)(Lb + l) * cS));
        }
        accT = wallred(accT);
        allred16(acc);
        if (lane < 16) sA[wId*17 + lane] = pick16(acc, lane);
        if (lane == 0) sA[wId*17 + 16] = accT;
        __syncthreads();
        if (comb) {
            const int half = wId >> 2;
            const int b0 = (half*4) * 17;
            float aT = sA[b0+16] + sA[b0+17+16] + sA[b0+34+16] + sA[b0+51+16];
            float aS = 0.f;
            if (lane < 16) aS = sA[b0+lane] + sA[b0+17+lane] + sA[b0+34+lane] + sA[b0+51+lane];
            float sum5 = wallred((lane < cS) ? y5v : 0.f);
            float sum6 = wallred((lane < cS) ? y6v : 0.f);
            float ssv = 0.f;
            float xb_p = 0.f, xb_ru = 0.f, xb_rd = 0.f;
            if (lane == 0) {
                float gp  = y1u - y2u + aT + z1;
                float gru = y1u - sum5;
                float grd = y2u - sum6;
                if (POW) {
                    stcg(&g_X[OX_P + u], gp); stcg(&g_X[OX_RU + u], gru); stcg(&g_X[OX_RD + u], grd);
                    ssv += gp*gp + gru*gru + grd*grd;
                    shp[half] = gp;
                } else {
                    float x = ldcg(&g_X[OX_P + u]);
                    float xn = fmaxf(x - tau*(Cost[u] + gp), 0.f);
                    xb_p = 2.f*xn - x;
                    stcg(&g_X[OX_P + u], xn); stcg(&g_XBP[u], xb_p); shp[half] = xb_p;
                    x = ldcg(&g_X[OX_RU + u]); xn = fmaxf(x - tau*(Cru[u] + gru), 0.f);
                    xb_ru = 2.f*xn - x;
                    stcg(&g_X[OX_RU + u], xn);
                    x = ldcg(&g_X[OX_RD + u]); xn = fmaxf(x - tau*(Crd[u] + grd), 0.f);
                    xb_rd = 2.f*xn - x;
                    stcg(&g_X[OX_RD + u], xn);
                }
            }
            if (!POW) {
                xb_ru = __shfl_sync(0xffffffffu, xb_ru, 0);
                xb_rd = __shfl_sync(0xffffffffu, xb_rd, 0);
            }
            if (lane < cS) {
                float gpu_ = y5v + aS + z2s;
                float gpd_ = y6v - aS - z2s;
                int iu = OX_PU + u*cS + lane, id = OX_PD + u*cS + lane;
                if (POW) {
                    stcg(&g_X[iu], gpu_); stcg(&g_X[id], gpd_);
                    ssv += gpu_*gpu_ + gpd_*gpd_;
                    shc[half*cS + lane] = gpu_ - gpd_;
                } else {
                    float x = ldcg(&g_X[iu]); float xn = fmaxf(x - tau*gpu_, 0.f);
                    float xbu = 2.f*xn - x; stcg(&g_X[iu], xn);
                    x = ldcg(&g_X[id]); xn = fmaxf(x - tau*gpd_, 0.f);
                    float xbd = 2.f*xn - x; stcg(&g_X[id], xn);
                    stcg(&g_XBC[u*cS + lane], xbu - xbd);
                    shc[half*cS + lane] = xbu - xbd;
                    float y5n = fmaxf(y5v + sig*(xbu - xb_ru), 0.f);
                    float y6n = fmaxf(y6v + sig*(xbd - xb_rd), 0.f);
                    stcg(&g_Y[OY5 + u*cS + lane], y5n);
                    stcg(&g_Y[OY6 + u*cS + lane], y6n);
                }
            }
            if (!POW && lane == 0) {
                float y1n = fmaxf(y1u + sig*(xb_p + xb_ru - Pmax[u]), 0.f);
                float y2n = fmaxf(y2u + sig*(xb_rd - xb_p), 0.f);
                stcg(&g_Y[OY1 + u], y1n); stcg(&g_Y[OY2 + u], y2n);
            }
            if (POW) {
                float w = wallred(ssv);
                if (lane == 0) sh8[half] = w;
            }
        }
        __syncthreads();
        if (wId == 0) {
            if (lane == 0) stcg(&g_part_p[blk], shp[0] + shp[1]);
            if (lane < cS) stcg(&g_part_c[blk*cS + lane], shc[lane] + shc[cS + lane]);
            if (POW && lane == 0) stcg(&g_part_ss[blk], sh8[0] + sh8[1]);
        }
    } else {
        for (int i = threadIdx.x; i < cL; i += NT) s78s_sh[i] = ldcg(&g_s78s[i]);
        __syncthreads();
        const int wn = (blk - 80)*8 + wId;   // 0..415, active < 400
        float agg_e = 0.f, agg_ss = 0.f;
        if (wn < cN) {
            float zs = ldcg(&g_z2sum);
            float a0 = 0.f;
            const float* r0 = g_PTT + (size_t)wn * cL;
#pragma unroll 4
            for (int l = lane; l < cL; l += 32) a0 = fmaf(r0[l], s78s_sh[l], a0);
            a0 = wallred(a0);
            if (lane == 0) {
                float gsu = a0 + zs, gsd = -a0 - zs;
                if (POW) {
                    stcg(&g_X[OX_SU + wn], gsu); stcg(&g_X[OX_SD + wn], gsd);
                    agg_ss = gsu*gsu + gsd*gsd;
                    agg_e  = gsu - gsd;
                } else {
                    float x = ldcg(&g_X[OX_SU + wn]); float xn = fmaxf(x - tau*(CVIOL + gsu), 0.f);
                    float xbu = 2.f*xn - x; stcg(&g_X[OX_SU + wn], xn);
                    x = ldcg(&g_X[OX_SD + wn]); xn = fmaxf(x - tau*(CVIOL + gsd), 0.f);
                    float xbd = 2.f*xn - x; stcg(&g_X[OX_SD + wn], xn);
                    stcg(&g_XBE[wn], xbu - xbd);
                    agg_e = xbu - xbd;
                }
            }
        }
        if (lane == 0) { sh8[wId] = agg_e; sh8b[wId] = agg_ss; }
        __syncthreads();
        if (wId == 0 && lane == 0) {
            float se = 0.f, ss = 0.f;
#pragma unroll
            for (int k = 0; k < 8; k++) { se += sh8[k]; ss += sh8b[k]; }
            stcg(&g_part_e[blk], se);
            if (POW) stcg(&g_part_ss[blk], ss);
        }
    }
}

// ---------------- Phase B ----------------
// l-part: blocks 0..127, 4 l/block, 2 warps per l (u/n halves, smem combine).
// POW: blocks 128..131 write u-y rows (scaled); eq-duals: block 128 warp 7.
template<bool POW>
__device__ __forceinline__ void phaseB(int blk, int wId, int lane, float sig,
                                       const float* __restrict__ PTDF,
                                       float* dsh_t, float* sdsh, float* psh, float* sB)
{
    float inv = 1.f;
    if (POW) {
        float a = 0.f;
#pragma unroll
        for (int k = 0; k < 4; k++) a += ldcg(&g_part_ss[lane + 32*k]);
        if (lane < 4) a += ldcg(&g_part_ss[128 + lane]);
        a = wallred(a);
        inv = rsqrtf(a);
    }
    if (blk < 128) {
        // ---- staging ----
        if (POW) {
            for (int c = threadIdx.x; c < (cU*cS/4); c += NT) {
                float4 a = ldcg4(reinterpret_cast<const float4*>(g_X + OX_PU) + c);
                float4 b = ldcg4(reinterpret_cast<const float4*>(g_X + OX_PD) + c);
                int u = c >> 2, s0 = (c & 3) * 4;
                dsh_t[(s0+0)*cU + u] = (a.x - b.x) * inv;
                dsh_t[(s0+1)*cU + u] = (a.y - b.y) * inv;
                dsh_t[(s0+2)*cU + u] = (a.z - b.z) * inv;
                dsh_t[(s0+3)*cU + u] = (a.w - b.w) * inv;
            }
            for (int i = threadIdx.x; i < cN; i += NT)
                sdsh[i] = (ldcg(&g_X[OX_SU + i]) - ldcg(&g_X[OX_SD + i])) * inv;
            for (int i = threadIdx.x; i < cU; i += NT)
                psh[i] = ldcg(&g_X[OX_P + i]) * inv;
        } else {
            for (int c = threadIdx.x; c < (cU*cS/4); c += NT) {
                float4 d = ldcg4(reinterpret_cast<const float4*>(g_XBC) + c);
                int u = c >> 2, s0 = (c & 3) * 4;
                dsh_t[(s0+0)*cU + u] = d.x;
                dsh_t[(s0+1)*cU + u] = d.y;
                dsh_t[(s0+2)*cU + u] = d.z;
                dsh_t[(s0+3)*cU + u] = d.w;
            }
            for (int i = threadIdx.x; i < cN; i += NT) sdsh[i] = ldcg(&g_XBE[i]);
            for (int i = threadIdx.x; i < cU; i += NT) psh[i] = ldcg(&g_XBP[i]);
        }
        __syncthreads();
        const int l = blk*4 + (wId >> 1);
        const int half = wId & 1;
        // prefetch duals on the combining (half==0) warp
        float y3 = 0.f, y4 = 0.f, y7 = 0.f, y8 = 0.f;
        if (!POW && half == 0) {
            y3 = ldcg(&g_Y[OY3 + l]);
            y4 = ldcg(&g_Y[OY4 + l]);
            if (lane < cS) {
                y7 = ldcg(&g_Y[OY7 + l*cS + lane]);
                y8 = ldcg(&g_Y[OY8 + l*cS + lane]);
            }
        }
        float accF = 0.f, accP = 0.f;
        float acc[16];
#pragma unroll
        for (int k = 0; k < 16; k++) acc[k] = 0.f;
        const float* hr = g_Hg + (size_t)l * cU;
        const int u0 = half * 80;
        for (int u = u0 + lane; u < u0 + 80; u += 32) {
            float h = hr[u];
            accF = fmaf(h, psh[u], accF);
            fma16sh_t(acc, h, dsh_t + u);
        }
        const float* pr = PTDF + (size_t)l * cN;
        const int n0 = half * 200;
#pragma unroll 2
        for (int n = n0 + lane; n < n0 + 200; n += 32) accP = fmaf(pr[n], sdsh[n], accP);
        accF = wallred(accF);
        accP = wallred(accP);
        allred16(acc);
        if (lane < 16) sB[wId*19 + lane] = pick16(acc, lane);
        if (lane == 0) { sB[wId*19 + 16] = accF; sB[wId*19 + 17] = accP; }
        __syncthreads();
        if (half == 0) {
            float fp = sB[wId*19 + 16] + sB[(wId+1)*19 + 16];
            float aP = sB[wId*19 + 17] + sB[(wId+1)*19 + 17];
            float aS = (lane < 16) ? (sB[wId*19 + lane] + sB[(wId+1)*19 + lane]) : 0.f;
            float base = fp + aP;
            float y3n, y4n;
            if (POW) { y3n = fp; y4n = -fp; }
            else {
                y3n = fmaxf(y3 + sig*( fp - g_c3[l]), 0.f);
                y4n = fmaxf(y4 + sig*(-fp - g_c4[l]), 0.f);
            }
            float s78v = 0.f;
            if (lane < cS) {
                float scen = aS + base;
                float y7n, y8n;
                if (POW) { y7n = scen; y8n = -scen; }
                else {
                    y7n = fmaxf(y7 + sig*( scen - g_b7[l*cS + lane]), 0.f);
                    y8n = fmaxf(y8 + sig*(-scen - g_b8[l*cS + lane]), 0.f);
                }
                stcg(&g_Y[OY7 + l*cS + lane], y7n);
                stcg(&g_Y[OY8 + l*cS + lane], y8n);
                s78v = y7n - y8n;
                stcg(&g_s78[l*cS + lane], s78v);
            }
            float s78s = wallred(s78v);
            if (lane == 0) {
                stcg(&g_Y[OY3 + l], y3n);
                stcg(&g_Y[OY4 + l], y4n);
                stcg(&g_s78s[l], s78s);
                stcg(&g_t[l], y3n - y4n + s78s);
            }
        }
    } else {
        if (POW) {
            const int base = (blk - 128)*40 + wId*5;
#pragma unroll
            for (int r = 0; r < 5; r++) {
                const int u = base + r;
                float ru = ldcg(&g_X[OX_RU + u]) * inv;
                float rd = ldcg(&g_X[OX_RD + u]) * inv;
                if (lane == 0) {
                    float p = ldcg(&g_X[OX_P + u]) * inv;
                    stcg(&g_Y[OY1 + u], p + ru);
                    stcg(&g_Y[OY2 + u], rd - p);
                }
                if (lane < cS) {
                    float pu = ldcg(&g_X[OX_PU + u*cS + lane]) * inv;
                    float pd = ldcg(&g_X[OX_PD + u*cS + lane]) * inv;
                    stcg(&g_Y[OY5 + u*cS + lane], pu - ru);
                    stcg(&g_Y[OY6 + u*cS + lane], pd - rd);
                }
            }
        }
        if (blk == 128 && wId == 7) {
            float sp = 0.f;
            for (int b = lane; b < 80; b += 32) sp += ldcg(&g_part_p[b]);
            sp = wallred(sp);
            float se = 0.f;
            for (int b = 80 + lane; b < NB; b += 32) se += ldcg(&g_part_e[b]);
            se = wallred(se);
            int s = lane & 15, h = lane >> 4;
            float sc = 0.f;
#pragma unroll
            for (int b = h*40; b < h*40 + 40; b++) sc += ldcg(&g_part_c[b*cS + s]);
            sc += __shfl_xor_sync(0xffffffffu, sc, 16);
            float ae2 = sc + se;
            float z2n = 0.f;
            if (lane < cS) {
                z2n = POW ? (ae2 * inv) : (ldcg(&g_z2[lane]) + sig*(ae2 - g_beq2[lane]));
                stcg(&g_z2[lane], z2n);
            }
            float zs = wallred((lane < cS) ? z2n : 0.f);
            if (lane == 0) {
                float z1n = POW ? (sp * inv) : (ldcg(&g_z1) + sig*(sp - g_beq1));
                stcg(&g_z1, z1n);
                stcg(&g_z2sum, zs);
            }
        }
    }
}

// ---------------- main persistent kernel ----------------
__global__ void __launch_bounds__(NT, 1)
opf_kernel(const float* __restrict__ w_scen, const float* __restrict__ Pmax,
           const float* __restrict__ Cost, const float* __restrict__ Cru,
           const float* __restrict__ Crd, const float* __restrict__ PTDF,
           const float* __restrict__ node_G, const float* __restrict__ node_W,
           const float* __restrict__ Pd, const float* __restrict__ w_exp,
           const float* __restrict__ Cap, float* __restrict__ out)
{
    __shared__ __align__(16) float dsh_t[cS*cU];
    __shared__ float sdsh[cN];
    __shared__ float psh[cU];
    __shared__ float s78s_sh[cL];
    __shared__ float sA[8*17];
    __shared__ float sB[8*19];
    __shared__ float shp[2], shc[2*cS], sh8[8], sh8b[8];

    const int blk  = blockIdx.x;
    const int tid  = blk * NT + threadIdx.x;
    const int wId  = threadIdx.x >> 5;
    const int lane = threadIdx.x & 31;
    const int gw   = blk * 8 + wId;
    unsigned rnd;
    {
        unsigned e;
        asm volatile("ld.global.cg.u32 %0, [%1];" : "=r"(e) : "l"(&g_epoch));
        rnd = e;
    }

    // ---- setup 1: index extraction + equality rhs ----
    if (gw < cU) {
        int u = gw, f = -1;
        for (int n = lane; n < cN; n += 32)
            if (node_G[n * cU + u] != 0.f) f = n;
#pragma unroll
        for (int o = 16; o; o >>= 1) f = max(f, __shfl_xor_sync(0xffffffffu, f, o));
        if (lane == 0) __stcg(&g_gidx[u], f);
    } else if (gw < cU + cW) {
        int w = gw - cU, f = -1;
        for (int n = lane; n < cN; n += 32)
            if (node_W[n * cW + w] != 0.f) f = n;
#pragma unroll
        for (int o = 16; o; o >>= 1) f = max(f, __shfl_xor_sync(0xffffffffu, f, o));
        if (lane == 0) __stcg(&g_widx[w], f);
    } else if (gw == cU + cW) {
        float a = 0.f;
        for (int n = lane; n < cN; n += 32) a += Pd[n];
        for (int w = lane; w < cW; w += 32) a -= w_exp[w];
        a = wallred(a);
        if (lane == 0) stcg(&g_beq1, a);
    } else if (gw > cU + cW && gw <= cU + cW + cS) {
        int s = gw - (cU + cW + 1);
        float a = 0.f;
        for (int w = lane; w < cW; w += 32) a += w_scen[s * cW + w];
        a = wallred(a);
        if (lane == 0) stcg(&g_beq2[s], -a);
    }
    gsync(++rnd);

    // ---- setup 2: materialize matrices, rhs vectors, init power-iter state ----
    for (int i = tid; i < cL * cU; i += NTH) {
        int l = i / cU, u = i - l * cU;
        float v = PTDF[l * cN + __ldcg(&g_gidx[u])];
        g_Hg[l * cU + u] = v;
        g_HgT[u * cL + l] = v;
    }
    for (int i = tid; i < cN * cL; i += NTH) {
        int n = i >> 9, l = i & (cL - 1);
        g_PTT[i] = PTDF[l * cN + n];
    }
    if (gw < cL) {
        int l = gw;
        const float* pr = PTDF + l * cN;
        float a = 0.f;
        for (int n = lane; n < cN; n += 32) a -= pr[n] * Pd[n];
        float hw0 = pr[__ldcg(&g_widx[lane])];
        float hw1 = pr[__ldcg(&g_widx[lane + 32])];
        a += hw0 * w_exp[lane] + hw1 * w_exp[lane + 32];
        float cf = wallred(a);
        float cap = Cap[l];
        float c3 = cap - cf, c4 = cap + cf;
        if (lane == 0) { g_c3[l] = c3; g_c4[l] = c4; }
        float bws = 0.f;
#pragma unroll 4
        for (int w = 0; w < 32; w++) {
            float h0 = __shfl_sync(0xffffffffu, hw0, w);
            float h1 = __shfl_sync(0xffffffffu, hw1, w);
            if (lane < cS)
                bws += h0 * w_scen[lane * cW + w] + h1 * w_scen[lane * cW + w + 32];
        }
        if (lane < cS) {
            g_b7[l * cS + lane] = c3 - bws;
            g_b8[l * cS + lane] = c4 + bws;
        }
    }
    // init v0 = ones + its partials (nv0 = 1, sum(p) per u-block = 2)
    for (int i = tid; i < XTOT; i += NTH) stcg(&g_X[i], 1.f);
    if (tid < NB) {
        stcg(&g_part_ss[tid], (tid == 0) ? 1.f : 0.f);
        stcg(&g_part_e[tid], 0.f);
        stcg(&g_part_p[tid], (tid < 80) ? 2.f : 0.f);
    }
    for (int i = tid; i < 80*cS; i += NTH) stcg(&g_part_c[i], 0.f);
    gsync(++rnd);

    // ---- power iteration for ||A|| (31 fused B/A pairs; norm folded into B) ----
#pragma unroll 1
    for (int it = 0; it <= NPOWER; it++) {
        phaseB<true>(blk, wId, lane, 0.f, PTDF, dsh_t, sdsh, psh, sB);
        gsync(++rnd);
        phaseA<true>(blk, wId, lane, 0.f, Cost, Cru, Crd, Pmax, sA, shp, shc, sh8, sh8b, s78s_sh);
        gsync(++rnd);
    }

    // ---- reset state + compute tau ----
    for (int i = tid; i < XTOT; i += NTH) stcg(&g_X[i], 0.f);
    for (int i = tid; i < cU; i += NTH) stcg(&g_XBP[i], 0.f);
    for (int i = tid; i < cU*cS; i += NTH) stcg(&g_XBC[i], 0.f);
    for (int i = tid; i < cN; i += NTH) stcg(&g_XBE[i], 0.f);
    for (int i = tid; i < YTOT; i += NTH) stcg(&g_Y[i], 0.f);
    for (int i = tid; i < cL * cS; i += NTH) stcg(&g_s78[i], 0.f);
    for (int i = tid; i < cL; i += NTH) { stcg(&g_s78s[i], 0.f); stcg(&g_t[i], 0.f); }
    if (tid == 0) {
        float a = 0.f;
        for (int b = 0; b < NB; b++) a += ldcg(&g_part_ss[b]);
        float Lop = sqrtf(sqrtf(a));
        stcg(&g_tau, 0.9f / Lop);
        stcg(&g_z1, 0.f); stcg(&g_z2sum, 0.f);
    }
    if (tid < cS) stcg(&g_z2[tid], 0.f);
    gsync(++rnd);

    const float tau = ldcg(&g_tau);

    // ---- PDHG main loop ----
#pragma unroll 1
    for (int it = 0; it < NITERS; it++) {
        phaseA<false>(blk, wId, lane, tau, Cost, Cru, Crd, Pmax, sA, shp, shc, sh8, sh8b, s78s_sh);
        gsync(++rnd);
        phaseB<false>(blk, wId, lane, tau, PTDF, dsh_t, sdsh, psh, sB);
        gsync(++rnd);
    }

    // ---- output ----
    if (blk < 128 && wId < 4) {
        int l = blk*4 + wId;
        const float* hr = g_Hg + (size_t)l * cU;
        float a = 0.f;
        for (int u = lane; u < cU; u += 32) a = fmaf(hr[u], ldcg(&g_X[OX_P + u]), a);
        a = wallred(a);
        if (lane == 0) {
            out[5600 + l] = g_c3[l] - a;   // f_up = Cap - flow
            out[6112 + l] = g_c4[l] + a;   // f_down = Cap + flow
        }
    } else if ((blk < 128 && wId == 4) || (blk < 32 && wId == 5)) {
        int u = (wId == 4) ? blk : (128 + blk);
        if (lane == 0) {
            out[u]       = ldcg(&g_X[OX_P + u]);
            out[160 + u] = ldcg(&g_X[OX_RU + u]);
            out[320 + u] = ldcg(&g_X[OX_RD + u]);
        }
        if (lane < cS) {
            out[480 + u*cS + lane]  = ldcg(&g_X[OX_PU + u*cS + lane]);
            out[3040 + u*cS + lane] = ldcg(&g_X[OX_PD + u*cS + lane]);
        }
    } else if (blk == 131 && wId == 7) {
        float a = 0.f;
        for (int i = lane; i < cU; i += 32)
            a += Cost[i] * ldcg(&g_X[OX_P + i]) + Cru[i] * ldcg(&g_X[OX_RU + i])
               + Crd[i] * ldcg(&g_X[OX_RD + i]);
        for (int i = lane; i < cN; i += 32)
            a += CVIOL * (ldcg(&g_X[OX_SU + i]) + ldcg(&g_X[OX_SD + i]));
        a = wallred(a);
        if (lane == 0) out[6624] = a;
    }

    // persist the barrier epoch for the next (stream-ordered) launch
    if (blk == 0 && threadIdx.x == 0) {
        asm volatile("st.global.cg.u32 [%0], %1;" :: "l"(&g_epoch), "r"(rnd) : "memory");
    }
}

extern "C" void kernel_launch(void* const* d_in, const int* in_sizes, int n_in,
                              void* d_out, int out_size) {
    const float* w_scen = (const float*)d_in[0];
    const float* Pmax   = (const float*)d_in[1];
    const float* Cost   = (const float*)d_in[2];
    const float* Cru    = (const float*)d_in[3];
    const float* Crd    = (const float*)d_in[4];
    const float* PTDF   = (const float*)d_in[5];
    const float* node_G = (const float*)d_in[6];
    const float* node_W = (const float*)d_in[7];
    // d_in[8] = node_L (identity, unused)
    const float* Pd     = (const float*)d_in[9];
    const float* w_exp  = (const float*)d_in[10];
    const float* Cap    = (const float*)d_in[11];
    float* out = (float*)d_out;
    (void)in_sizes; (void)n_in; (void)out_size;

    opf_kernel<<<NB, NT>>>(w_scen, Pmax, Cost, Cru, Crd, PTDF,
                           node_G, node_W, Pd, w_exp, Cap, out);
}